// round 10
// baseline (speedup 1.0000x reference)
#include <cuda_runtime.h>
#include <cuda_bf16.h>
#include <stdint.h>

#define DEVINL __device__ __forceinline__

// ---------------------------------------------------------------------------
// Dims: z[N,64] -> h1[N,128] -> h2[N,128] -> b[N,12(pad16)]
// Single-pass tf32 (m16n8k8). W2/W3 k-rows tau-permuted per 8-group so the
// accumulator layout equals the next layer's A-fragment layout.
// Each warp owns 32 rows (2 m-tiles) -> weight LDSM traffic halved per row.
// ---------------------------------------------------------------------------

// fp32 weight pitches; pitch mod 128B == 16 so ldmatrix rows are conflict-free
static constexpr int P1B = 272;   // W1 k=64  ([128][68] f32)
static constexpr int P2B = 528;   // W2/W3 k=128 ([.][132] f32)
static constexpr int P1  = 68;
static constexpr int P2  = 132;

static constexpr unsigned OFF_W1 = 0;
static constexpr unsigned OFF_W2 = 34816;
static constexpr unsigned OFF_W3 = 102400;
static constexpr unsigned WB     = 110848;

static constexpr unsigned B1O = WB;            // 128 f32
static constexpr unsigned B2O = WB + 512;      // 128 f32
static constexpr unsigned B3O = WB + 1024;     // 16 f32
static constexpr unsigned SMT = WB + 1024 + 64;

__device__ __align__(16) unsigned char g_wb[WB];

// ---------------------------------------------------------------------------
DEVINL uint32_t smem_u32(const void* p) {
    uint32_t a;
    asm("{ .reg .u64 t; cvta.to.shared.u64 t, %1; cvt.u32.u64 %0, t; }" : "=r"(a) : "l"(p));
    return a;
}

#define LDSM4(R, ADDR) \
    asm volatile("ldmatrix.sync.aligned.m8n8.x4.shared.b16 {%0,%1,%2,%3},[%4];" \
                 : "=r"((R)[0]), "=r"((R)[1]), "=r"((R)[2]), "=r"((R)[3]) : "r"(ADDR))

#define MMAT(C, A0, A1, A2, A3, B0, B1) \
    asm volatile("mma.sync.aligned.m16n8k8.row.col.f32.tf32.tf32.f32 " \
                 "{%0,%1,%2,%3},{%4,%5,%6,%7},{%8,%9},{%0,%1,%2,%3};" \
                 : "+f"((C)[0]), "+f"((C)[1]), "+f"((C)[2]), "+f"((C)[3]) \
                 : "r"(A0), "r"(A1), "r"(A2), "r"(A3), "r"(B0), "r"(B1))

DEVINL uint32_t cvt_tf32(float f) {
    uint32_t u;
    asm("cvt.rna.tf32.f32 %0, %1;" : "=r"(u) : "f"(f));
    return u;
}

// ---------------------------------------------------------------------------
// prep: weights -> [n][k] tf32-rounded fp32, W2/W3 k-rows tau-permuted
// ---------------------------------------------------------------------------
__global__ void tastenet_prep(const float* __restrict__ W1,
                              const float* __restrict__ W2,
                              const float* __restrict__ W3) {
    int i = blockIdx.x * blockDim.x + threadIdx.x;
    float* w1 = (float*)(g_wb + OFF_W1);
    float* w2 = (float*)(g_wb + OFF_W2);
    float* w3 = (float*)(g_wb + OFF_W3);

    if (i < 128 * 64) {                       // W1 (64,128) -> [n][k], natural
        int n = i >> 6, k = i & 63;
        uint32_t u = cvt_tf32(W1[k * 128 + n]);
        w1[n * P1 + k] = __uint_as_float(u);
    }
    if (i < 128 * 128) {                      // W2 (128,128) -> [n][p], k=tau(p)
        int n = i >> 7, p = i & 127;
        int pg = p & 7;
        int kl = (pg < 4) ? (2 * pg) : (2 * (pg - 4) + 1);
        int k = (p & ~7) + kl;
        uint32_t u = cvt_tf32(W2[k * 128 + n]);
        w2[n * P2 + p] = __uint_as_float(u);
    }
    if (i < 16 * 128) {                       // W3 (128,12) pad n to 16
        int n = i >> 7, p = i & 127;
        int pg = p & 7;
        int kl = (pg < 4) ? (2 * pg) : (2 * (pg - 4) + 1);
        int k = (p & ~7) + kl;
        float w = (n < 12) ? W3[k * 12 + n] : 0.f;
        uint32_t u = cvt_tf32(w);
        w3[n * P2 + p] = __uint_as_float(u);
    }
}

// ---------------------------------------------------------------------------
// main persistent kernel: 256 threads, each warp independently owns 32 rows
// (2 m-tiles) per super-tile of 256 rows. No intra-loop synchronization.
// ---------------------------------------------------------------------------
__global__ void __launch_bounds__(256, 1)
tastenet_main(const float* __restrict__ x, const float* __restrict__ z,
              const float* __restrict__ b1, const float* __restrict__ b2,
              const float* __restrict__ b3, float* __restrict__ out,
              int num_st) {
    extern __shared__ __align__(16) unsigned char smem[];
    const int tid = threadIdx.x;

    // ---- one-time: copy weight image + biases into smem ----
    {
        const float4* s = reinterpret_cast<const float4*>(g_wb);
        float4* d = reinterpret_cast<float4*>(smem);
        for (int i = tid; i < (int)(WB / 16); i += 256) d[i] = s[i];
        float* sb1 = (float*)(smem + B1O);
        float* sb2 = (float*)(smem + B2O);
        float* sb3 = (float*)(smem + B3O);
        if (tid < 128) { sb1[tid] = b1[tid]; sb2[tid] = b2[tid]; }
        if (tid < 16)  sb3[tid] = (tid < 12) ? b3[tid] : 0.f;
    }
    __syncthreads();

    const uint32_t sb = smem_u32(smem);
    const int w = tid >> 5, l = tid & 31;
    const int g = l >> 2, q = l & 3;

    // B-operand ldmatrix lane bases (tf32-pair trick: row l&7, float-col 4*(l>>3))
    const uint32_t bW1 = sb + OFF_W1 + (l & 7) * P1B + (l >> 3) * 16;
    const uint32_t bW2 = sb + OFF_W2 + (l & 7) * P2B + (l >> 3) * 16;
    const uint32_t bW3 = sb + OFF_W3 + (l & 7) * P2B + (l >> 3) * 16;

    const float* sb3 = (const float*)(smem + B3O);
    const unsigned char* b1p = smem + B1O;
    const unsigned char* b2p = smem + B2O;

    for (int st = blockIdx.x; st < num_st; st += gridDim.x) {
        const int base = st * 256 + w * 32;   // warp's first row

        // ---- x prefetch for the epilogue (quad layout) ----
        float xp[2][2][3];
#pragma unroll
        for (int mt = 0; mt < 2; mt++)
#pragma unroll
            for (int rs = 0; rs < 2; rs++) {
                const float* xr = x + (size_t)(base + mt * 16 + g + rs * 8) * 9;
                xp[mt][rs][0] = xr[q];
                xp[mt][rs][1] = xr[4 + q];
                xp[mt][rs][2] = xr[8];
            }

        // ---- build layer-1 A fragments directly from gmem z ----
        uint32_t A1[8][2][4];
#pragma unroll
        for (int mt = 0; mt < 2; mt++) {
            const float* z0 = z + (size_t)(base + mt * 16 + g) * 64 + q;
            const float* z8 = z0 + 8 * 64;
#pragma unroll
            for (int kt = 0; kt < 8; kt++) {
                A1[kt][mt][0] = cvt_tf32(z0[8 * kt]);
                A1[kt][mt][1] = cvt_tf32(z8[8 * kt]);
                A1[kt][mt][2] = cvt_tf32(z0[8 * kt + 4]);
                A1[kt][mt][3] = cvt_tf32(z8[8 * kt + 4]);
            }
        }

        // ---- layer 1: K=64, full N=128, 2 m-tiles ----
        float acc[16][2][4];
#pragma unroll
        for (int n = 0; n < 16; n++)
#pragma unroll
            for (int mt = 0; mt < 2; mt++)
#pragma unroll
                for (int c = 0; c < 4; c++) acc[n][mt][c] = 0.f;

#pragma unroll
        for (int kp = 0; kp < 4; kp++) {
#pragma unroll
            for (int jb = 0; jb < 4; jb++) {
                uint32_t B[4][4];
#pragma unroll
                for (int j = 0; j < 4; j++)
                    LDSM4(B[j], bW1 + (4 * jb + j) * 8 * P1B + kp * 64);
#pragma unroll
                for (int j = 0; j < 4; j++)
#pragma unroll
                    for (int mt = 0; mt < 2; mt++)
                        MMAT(acc[4 * jb + j][mt],
                             A1[2 * kp][mt][0], A1[2 * kp][mt][1],
                             A1[2 * kp][mt][2], A1[2 * kp][mt][3],
                             B[j][0], B[j][1]);
#pragma unroll
                for (int j = 0; j < 4; j++)
#pragma unroll
                    for (int mt = 0; mt < 2; mt++)
                        MMAT(acc[4 * jb + j][mt],
                             A1[2 * kp + 1][mt][0], A1[2 * kp + 1][mt][1],
                             A1[2 * kp + 1][mt][2], A1[2 * kp + 1][mt][3],
                             B[j][2], B[j][3]);
            }
        }

        // ---- h1 = relu(acc+b1) -> A2 frags (registers only, tau mapping) ----
        uint32_t A2[16][2][4];
#pragma unroll
        for (int np = 0; np < 16; np++) {
            float2 bb = *(const float2*)(b1p + (8 * np + 2 * q) * 4);
#pragma unroll
            for (int mt = 0; mt < 2; mt++) {
                float v0 = fmaxf(acc[np][mt][0] + bb.x, 0.f);
                float v1 = fmaxf(acc[np][mt][1] + bb.y, 0.f);
                float v2 = fmaxf(acc[np][mt][2] + bb.x, 0.f);
                float v3 = fmaxf(acc[np][mt][3] + bb.y, 0.f);
                A2[np][mt][0] = cvt_tf32(v0);
                A2[np][mt][1] = cvt_tf32(v2);
                A2[np][mt][2] = cvt_tf32(v1);
                A2[np][mt][3] = cvt_tf32(v3);
            }
        }

        // ---- layer-3 accumulators (filled incrementally per k-half) ----
        float a3[2][2][4];
#pragma unroll
        for (int mt = 0; mt < 2; mt++)
#pragma unroll
            for (int n = 0; n < 2; n++)
#pragma unroll
                for (int c = 0; c < 4; c++) a3[mt][n][c] = 0.f;

        // ---- layer 2 in two sequential N-half phases + partial layer 3 ----
#pragma unroll
        for (int h = 0; h < 2; h++) {
            float ap[8][2][4];
#pragma unroll
            for (int n = 0; n < 8; n++)
#pragma unroll
                for (int mt = 0; mt < 2; mt++)
#pragma unroll
                    for (int c = 0; c < 4; c++) ap[n][mt][c] = 0.f;

#pragma unroll
            for (int kp = 0; kp < 8; kp++) {
#pragma unroll
                for (int jb = 0; jb < 2; jb++) {
                    uint32_t B[4][4];
#pragma unroll
                    for (int j = 0; j < 4; j++)
                        LDSM4(B[j], bW2 + (8 * h + 4 * jb + j) * 8 * P2B + kp * 64);
#pragma unroll
                    for (int j = 0; j < 4; j++)
#pragma unroll
                        for (int mt = 0; mt < 2; mt++)
                            MMAT(ap[4 * jb + j][mt],
                                 A2[2 * kp][mt][0], A2[2 * kp][mt][1],
                                 A2[2 * kp][mt][2], A2[2 * kp][mt][3],
                                 B[j][0], B[j][1]);
#pragma unroll
                    for (int j = 0; j < 4; j++)
#pragma unroll
                        for (int mt = 0; mt < 2; mt++)
                            MMAT(ap[4 * jb + j][mt],
                                 A2[2 * kp + 1][mt][0], A2[2 * kp + 1][mt][1],
                                 A2[2 * kp + 1][mt][2], A2[2 * kp + 1][mt][3],
                                 B[j][2], B[j][3]);
                }
            }

            // transition of this N-half: relu(ap+b2) -> A3 k-half frags
            uint32_t A3[8][2][4];
#pragma unroll
            for (int j = 0; j < 8; j++) {
                float2 bb = *(const float2*)(b2p + (8 * (8 * h + j) + 2 * q) * 4);
#pragma unroll
                for (int mt = 0; mt < 2; mt++) {
                    float v0 = fmaxf(ap[j][mt][0] + bb.x, 0.f);
                    float v1 = fmaxf(ap[j][mt][1] + bb.y, 0.f);
                    float v2 = fmaxf(ap[j][mt][2] + bb.x, 0.f);
                    float v3 = fmaxf(ap[j][mt][3] + bb.y, 0.f);
                    A3[j][mt][0] = cvt_tf32(v0);
                    A3[j][mt][1] = cvt_tf32(v2);
                    A3[j][mt][2] = cvt_tf32(v1);
                    A3[j][mt][3] = cvt_tf32(v3);
                }
            }

            // partial layer 3 over this k-half, then A3 regs die
#pragma unroll
            for (int kpl = 0; kpl < 4; kpl++) {
                uint32_t B0[4], B1r[4];
                LDSM4(B0,  bW3 + (4 * h + kpl) * 64);
                LDSM4(B1r, bW3 + 8 * P2B + (4 * h + kpl) * 64);
#pragma unroll
                for (int mt = 0; mt < 2; mt++) {
                    MMAT(a3[mt][0], A3[2 * kpl][mt][0], A3[2 * kpl][mt][1],
                         A3[2 * kpl][mt][2], A3[2 * kpl][mt][3], B0[0], B0[1]);
                    MMAT(a3[mt][1], A3[2 * kpl][mt][0], A3[2 * kpl][mt][1],
                         A3[2 * kpl][mt][2], A3[2 * kpl][mt][3], B1r[0], B1r[1]);
                    MMAT(a3[mt][0], A3[2 * kpl + 1][mt][0], A3[2 * kpl + 1][mt][1],
                         A3[2 * kpl + 1][mt][2], A3[2 * kpl + 1][mt][3], B0[2], B0[3]);
                    MMAT(a3[mt][1], A3[2 * kpl + 1][mt][0], A3[2 * kpl + 1][mt][1],
                         A3[2 * kpl + 1][mt][2], A3[2 * kpl + 1][mt][3], B1r[2], B1r[3]);
                }
            }
        }

        // ---- epilogue per m-tile: clamps, taste*x segment sums, store ----
#pragma unroll
        for (int mt = 0; mt < 2; mt++) {
            float b3A = sb3[2 * q], b3B = sb3[2 * q + 1];
            float b3C = sb3[8 + 2 * q], b3D = sb3[9 + 2 * q];
            const int row0 = base + mt * 16 + g;
#pragma unroll
            for (int rs = 0; rs < 2; rs++) {
                float vA = a3[mt][0][rs * 2 + 0] + b3A;   // col 2q
                float vB = a3[mt][0][rs * 2 + 1] + b3B;   // col 2q+1
                float vC = a3[mt][1][rs * 2 + 0] + b3C;   // col 8+2q
                float vD = a3[mt][1][rs * 2 + 1] + b3D;   // col 9+2q
                if (q < 3)  vA = fminf(vA, 0.f);
                vB = fminf(vB, 0.f);
                if (q == 0) vC = fminf(vC, 0.f);

                int row = row0 + rs * 8;
                float l0 = xp[mt][rs][0];
                float l1 = xp[mt][rs][1];
                float l2 = xp[mt][rs][2];

                unsigned basel = (unsigned)(l & ~3);
                float xAl = __shfl_sync(0xffffffffu, l0, basel | ((2 * q) & 3));
                float xAh = __shfl_sync(0xffffffffu, l1, basel | ((2 * q) & 3));
                float xBl = __shfl_sync(0xffffffffu, l0, basel | ((2 * q + 1) & 3));
                float xBh = __shfl_sync(0xffffffffu, l1, basel | ((2 * q + 1) & 3));
                float xA = (q < 2) ? xAl : xAh;
                float xB = (q < 2) ? xBl : xBh;

                float p0 = 0.f, p1 = 0.f, p2 = 0.f;
                if (q == 0) {
                    p0 = fmaf(xA, vA, xB * vB) + vD;
                    p2 = l2 * vC;
                } else if (q == 1) {
                    p0 = xA * vA;
                    p1 = xB * vB + vC;
                    p2 = vD;
                } else if (q == 2) {
                    p1 = fmaf(xA, vA, xB * vB);
                } else {
                    p2 = fmaf(xA, vA, xB * vB);
                }
                p0 += __shfl_xor_sync(0xffffffffu, p0, 1);
                p0 += __shfl_xor_sync(0xffffffffu, p0, 2);
                p1 += __shfl_xor_sync(0xffffffffu, p1, 1);
                p1 += __shfl_xor_sync(0xffffffffu, p1, 2);
                p2 += __shfl_xor_sync(0xffffffffu, p2, 1);
                p2 += __shfl_xor_sync(0xffffffffu, p2, 2);
                if (q < 3) {
                    float val = (q == 0) ? p0 : (q == 1) ? p1 : p2;
                    out[(size_t)row * 3 + q] = val;
                }
            }
        }
    }
}

// ---------------------------------------------------------------------------
// kernel_launch
// ---------------------------------------------------------------------------
extern "C" void kernel_launch(void* const* d_in, const int* in_sizes, int n_in,
                              void* d_out, int out_size) {
    const float* x  = (const float*)d_in[0];
    const float* z  = (const float*)d_in[1];
    const float* W1 = (const float*)d_in[2];
    const float* b1 = (const float*)d_in[3];
    const float* W2 = (const float*)d_in[4];
    const float* b2 = (const float*)d_in[5];
    const float* W3 = (const float*)d_in[6];
    const float* b3 = (const float*)d_in[7];
    float* out = (float*)d_out;

    const int n = in_sizes[1] / 64;
    const int num_st = n / 256;              // 256-row super-tiles

    tastenet_prep<<<64, 256>>>(W1, W2, W3);

    static int smem_set = 0;
    if (!smem_set) {
        cudaFuncSetAttribute(tastenet_main,
                             cudaFuncAttributeMaxDynamicSharedMemorySize, SMT);
        smem_set = 1;
    }
    int dev = 0, sms = 148;
    cudaGetDevice(&dev);
    cudaDeviceGetAttribute(&sms, cudaDevAttrMultiProcessorCount, dev);
    int grid = (sms < num_st) ? sms : num_st;
    if (grid < 1) grid = 1;

    tastenet_main<<<grid, 256, SMT>>>(x, z, b1, b2, b3, out, num_st);
}